// round 9
// baseline (speedup 1.0000x reference)
#include <cuda_runtime.h>
#include <cstdint>

#define T_STEPS 2048
#define NB 32      // batch
#define NI 64      // input dim
#define NM 1024    // M == H
#define NBLK 144
#define NTHR 512

typedef unsigned long long u64;

// ---------------- device storage (static, no allocation) ----------------
__device__ __align__(16) float g_Vm1T[NM*NM];
__device__ __align__(16) float g_Vm2T[NM*NM];
__device__ __align__(16) float g_Pm2m1T[NM*NM];   // (Wm2@Vm1)^T
__device__ __align__(16) float g_Wh1T[NM*NM];
__device__ __align__(16) float g_Q1T[NM*NM];      // (Wmh1@Vm2)^T
__device__ __align__(16) float g_Q2T[NM*NM];      // (Wmh1@Wm2@Vm1)^T
__device__ __align__(16) float g_Win2T[NM*NM];
__device__ __align__(16) float g_Wh2T[NM*NM];
__device__ __align__(16) float g_Wmh2T[NM*NM];
__device__ __align__(16) float g_Wm1T[NI*NM];
__device__ __align__(16) float g_Pm2xT[NI*NM];    // (Wm2@Wm1)^T
__device__ __align__(16) float g_Win1effT[NI*NM]; // (Win1 + Wmh1@Wm2@Wm1)^T
__device__ __align__(16) float g_xT[T_STEPS*NI*NB];
// h states, layout [n][b], double buffered
__device__ __align__(16) float g_h1T[2][NM*NB];
__device__ __align__(16) float g_h2T[2][NM*NB];
// partial products, [parity][mm][n][b]
__device__ __align__(16) float g_partial[2][9][NM*NB];
// striped barrier counters (reset in-graph by zero_states_kernel)
__device__ unsigned g_bar1[8];
__device__ unsigned g_bar2[4];

#define FMA2(acc, a, b) asm("fma.rn.f32x2 %0, %1, %2, %0;" : "+l"(acc) : "l"(a), "l"(b))
#define ADD2(acc, b)    asm("add.rn.f32x2 %0, %0, %1;"     : "+l"(acc) : "l"(b))
#define PACK2(w2, wu)   asm("mov.b64 %0, {%1, %1};"        : "=l"(w2)  : "r"(wu))

__device__ __forceinline__ unsigned ld_acq(const unsigned* p) {
    unsigned v;
    asm volatile("ld.global.acquire.gpu.u32 %0, [%1];" : "=r"(v) : "l"(p) : "memory");
    return v;
}
__device__ __forceinline__ void red_add(unsigned* p) {
    asm volatile("red.global.add.u32 [%0], 1;" :: "l"(p) : "memory");
}

// ---------------- setup kernels (exactly 5 launches before persist) ----------------

__global__ void transp_all_kernel(const float* __restrict__ Vm1, const float* __restrict__ Vm2,
                                  const float* __restrict__ Wh1, const float* __restrict__ Win2,
                                  const float* __restrict__ Wh2, const float* __restrict__ Wmh2,
                                  const float* __restrict__ Wm1) {
    const float* in; float* out; int C = NM;
    switch (blockIdx.y) {
        case 0: in = Vm1;  out = g_Vm1T;  break;
        case 1: in = Vm2;  out = g_Vm2T;  break;
        case 2: in = Wh1;  out = g_Wh1T;  break;
        case 3: in = Win2; out = g_Win2T; break;
        case 4: in = Wh2;  out = g_Wh2T;  break;
        case 5: in = Wmh2; out = g_Wmh2T; break;
        default:in = Wm1;  out = g_Wm1T;  C = NI; break;
    }
    int idx = blockIdx.x * 256 + threadIdx.x;
    if (idx < NM * C) {
        int r = idx / C, c = idx % C;
        out[(size_t)c * NM + r] = in[idx];
    }
}

__device__ __forceinline__ void gemm_pre_body(const float* __restrict__ X, const float* __restrict__ Y,
                                              const float* __restrict__ Cm, float* __restrict__ out,
                                              int N, int J, int K, int transY, int addC) {
    __shared__ float As[64][17];
    __shared__ float Bs[16][68];
    int tx = threadIdx.x, ty = threadIdx.y;
    int tid = ty * 16 + tx;
    int n0 = blockIdx.x * 64, k0 = blockIdx.y * 64;
    float c[4][4];
    #pragma unroll
    for (int i = 0; i < 4; i++)
        #pragma unroll
        for (int l = 0; l < 4; l++) c[i][l] = 0.f;

    for (int jt = 0; jt < J; jt += 16) {
        for (int e = tid; e < 1024; e += 256) {
            int r = e >> 4, cc = e & 15;
            As[r][cc] = transY ? Y[(size_t)(k0 + r) * J + jt + cc]
                               : Y[(size_t)(jt + cc) * K + k0 + r];
        }
        for (int e = tid; e < 1024; e += 256) {
            int jj = e >> 6, nn = e & 63;
            Bs[jj][nn] = X[(size_t)(n0 + nn) * J + jt + jj];
        }
        __syncthreads();
        #pragma unroll
        for (int j = 0; j < 16; j++) {
            float a[4], b[4];
            #pragma unroll
            for (int i = 0; i < 4; i++) a[i] = As[ty * 4 + i][j];
            #pragma unroll
            for (int i = 0; i < 4; i++) b[i] = Bs[j][tx * 4 + i];
            #pragma unroll
            for (int i = 0; i < 4; i++)
                #pragma unroll
                for (int l = 0; l < 4; l++) c[i][l] += a[i] * b[l];
        }
        __syncthreads();
    }
    #pragma unroll
    for (int i = 0; i < 4; i++)
        #pragma unroll
        for (int l = 0; l < 4; l++) {
            int k = k0 + ty * 4 + i, n = n0 + tx * 4 + l;
            float v = c[i][l];
            if (addC) v += Cm[(size_t)n * K + k];
            out[(size_t)k * N + n] = v;
        }
}

__global__ void pre_wave1_kernel(const float* __restrict__ Wm2, const float* __restrict__ Vm1,
                                 const float* __restrict__ Wmh1, const float* __restrict__ Vm2,
                                 const float* __restrict__ Wm1) {
    if (blockIdx.z == 0)      gemm_pre_body(Wm2,  Vm1, nullptr, g_Pm2m1T, NM, NM, NM, 0, 0);
    else if (blockIdx.z == 1) gemm_pre_body(Wmh1, Vm2, nullptr, g_Q1T,    NM, NM, NM, 0, 0);
    else { if (blockIdx.y > 0) return;
           gemm_pre_body(Wm2,  Wm1, nullptr, g_Pm2xT,  NM, NM, NI, 0, 0); }
}

__global__ void pre_wave2_kernel(const float* __restrict__ Wmh1, const float* __restrict__ Win1) {
    if (blockIdx.z == 0)      gemm_pre_body(Wmh1, g_Pm2m1T, nullptr, g_Q2T,     NM, NM, NM, 1, 0);
    else { if (blockIdx.y > 0) return;
           gemm_pre_body(Wmh1, g_Pm2xT, Win1, g_Win1effT, NM, NM, NI, 1, 1); }
}

__global__ void xtrans_kernel(const float* __restrict__ x) {
    int idx = blockIdx.x * 256 + threadIdx.x;
    if (idx < NB * T_STEPS * NI) {
        int b = idx >> 17;
        int r = idx & 131071;
        int tt = r >> 6;
        int i = r & 63;
        g_xT[tt * (NI * NB) + i * NB + b] = x[idx];
    }
}

// zero h states + barrier counters (runs inside the graph -> resets every replay)
__global__ void zero_states_kernel() {
    int i = blockIdx.x * 256 + threadIdx.x;
    if (i < NM * NB * 2) {
        ((float*)g_h1T)[i] = 0.f;
        ((float*)g_h2T)[i] = 0.f;
    }
    if (i < 8) g_bar1[i] = 0u;
    if (i < 4) g_bar2[i] = 0u;
}

// ---------------- persistent kernel ----------------
// 144 blocks x 512 threads (1 CTA/SM). Block = (mm = bx>>4, 64-n slice = bx&15).
// 16 warps = 8 kq (128 k each) x 2 n-halves. Warp: 32 n (lane) x 32 b = 16 f32x2 acc.

// one k-step: 8 broadcast LDS.128 (full 32-b row) + 16 FFMA2
__device__ __forceinline__ void fma16(u64* acc, const float* row, float wv) {
    uint32_t wu = __float_as_uint(wv);
    u64 w2; PACK2(w2, wu);
    const ulonglong2* ap = (const ulonglong2*)row;
    ulonglong2 q0 = ap[0], q1 = ap[1], q2 = ap[2], q3 = ap[3];
    ulonglong2 q4 = ap[4], q5 = ap[5], q6 = ap[6], q7 = ap[7];
    FMA2(acc[0],  w2, q0.x); FMA2(acc[1],  w2, q0.y);
    FMA2(acc[2],  w2, q1.x); FMA2(acc[3],  w2, q1.y);
    FMA2(acc[4],  w2, q2.x); FMA2(acc[5],  w2, q2.y);
    FMA2(acc[6],  w2, q3.x); FMA2(acc[7],  w2, q3.y);
    FMA2(acc[8],  w2, q4.x); FMA2(acc[9],  w2, q4.y);
    FMA2(acc[10], w2, q5.x); FMA2(acc[11], w2, q5.y);
    FMA2(acc[12], w2, q6.x); FMA2(acc[13], w2, q6.y);
    FMA2(acc[14], w2, q7.x); FMA2(acc[15], w2, q7.y);
}

// wait helpers: tid0 polls, block-wide via __syncthreads
__device__ __forceinline__ void wait1_block(unsigned target) {
    if (threadIdx.x == 0) {
        unsigned s;
        do {
            s = 0;
            #pragma unroll
            for (int i = 0; i < 8; i++) s += ld_acq(&g_bar1[i]);
        } while (s < target);
    }
    __syncthreads();
}
__device__ __forceinline__ void wait2_block(unsigned target) {
    if (threadIdx.x == 0) {
        unsigned s;
        do {
            s = 0;
            #pragma unroll
            for (int i = 0; i < 4; i++) s += ld_acq(&g_bar2[i]);
        } while (s < target);
    }
    __syncthreads();
}

extern "C" __global__ void __launch_bounds__(NTHR, 1)
persist_kernel(const float* __restrict__ b1, const float* __restrict__ b2,
               float* __restrict__ out) {
    extern __shared__ float sA[];           // 128 KB state + 8 KB sX
    float* sX = sA + NM * NB;
    __shared__ float tile[32 * 33];

    const int tid  = threadIdx.x;
    const int w    = tid >> 5, lane = tid & 31;
    const int kq   = w >> 1;                // 0..7
    const int nh   = w & 1;                 // 0..1
    const int mm   = blockIdx.x >> 4;
    const int blk  = blockIdx.x & 15;
    const int n    = blk * 64 + nh * 32 + lane;
    const int nloc = nh * 32 + lane;

    const bool hasX  = (mm == 0) || (mm == 1) || (mm == 3);
    const bool isH1C = (mm == 2) || (mm == 5);              // h1 combiners
    const bool isH2C = (mm == 4) || (mm == 8);              // h2 combiners
    const bool isHblk = (mm == 3) || (mm == 6) || (mm == 7);
    const int  cblk  = ((mm == 2 || mm == 4) ? blk : 16 + blk);
    const int  n0c   = cblk * 32;
    const int  cw    = tid >> 5;            // combine warp id

    const float *W, *Wx = 0;
    switch (mm) {
        case 0: W = g_Vm1T;   Wx = g_Wm1T;     break;
        case 1: W = g_Vm2T;   Wx = g_Pm2xT;    break;
        case 2: W = g_Pm2m1T;                  break;
        case 3: W = g_Wh1T;   Wx = g_Win1effT; break;
        case 4: W = g_Q1T;                     break;
        case 5: W = g_Q2T;                     break;
        case 6: W = g_Win2T;                   break;
        case 7: W = g_Wh2T;                    break;
        default:W = g_Wmh2T;                   break;
    }

    u64 acc[16];
    #pragma unroll
    for (int i = 0; i < 16; i++) acc[i] = 0ull;

    // ---- pre-loop x-phase for t = 0 ----
    if (hasX) {
        const float4* xs = (const float4*)g_xT;      // t = 0
        ((float4*)sX)[tid] = xs[tid];                // 2048 floats
        __syncthreads();
        const float* wx = Wx + (size_t)(kq * 8) * NM + n;
        #pragma unroll
        for (int u = 0; u < 8; u++)
            fma16(acc, sX + (kq * 8 + u) * 32, __ldg(wx + (size_t)u * NM));
    }

    for (int t = 0; t <= T_STEPS; t++) {
        const bool finalIter = (t == T_STEPS);
        const int  par = t & 1;

        if (finalIter && !(mm == 4 || mm == 6 || mm == 7 || mm == 8)) {
            if (tid == 0) { __threadfence(); red_add(&g_bar1[blockIdx.x & 7]); }
            return;
        }
        const bool runMain = !finalIter || (mm == 6) || (mm == 7) || (mm == 8);

        if (runMain) {
            // ---- stage A into smem ----
            if (t == 0) {
                float4 z = make_float4(0.f, 0.f, 0.f, 0.f);
                #pragma unroll
                for (int i = 0; i < 16; i++) ((float4*)sA)[tid + i * NTHR] = z;
            } else {
                const int sp = (t - 1) & 1;
                float4* dst = (float4*)sA;
                if (mm == 0 || mm == 2 || mm == 5) {
                    const float4* s = (const float4*)g_partial[sp][0];
                    #pragma unroll
                    for (int i = 0; i < 16; i++) dst[tid + i * NTHR] = s[tid + i * NTHR];
                } else if (mm == 1 || mm == 4 || mm == 8) {
                    const float4* s1 = (const float4*)g_partial[sp][1];
                    const float4* s2 = (const float4*)g_partial[sp][2];
                    #pragma unroll
                    for (int i = 0; i < 16; i++) {
                        float4 a = s1[tid + i * NTHR], b = s2[tid + i * NTHR];
                        dst[tid + i * NTHR] = make_float4(a.x + b.x, a.y + b.y, a.z + b.z, a.w + b.w);
                    }
                } else {
                    const float4* s = (const float4*)((mm == 7) ? g_h2T[par] : g_h1T[par]);
                    #pragma unroll
                    for (int i = 0; i < 16; i++) dst[tid + i * NTHR] = s[tid + i * NTHR];
                }
            }
            __syncthreads();

            // ---- main 128-k loop, depth-4 weight prefetch ----
            {
                const float* wp  = W + (size_t)(kq * 128) * NM + n;
                const float* saw = sA + (kq * 128) * 32;
                float pf[4];
                #pragma unroll
                for (int u = 0; u < 4; u++) pf[u] = __ldg(wp + (size_t)u * NM);
                for (int kc = 0; kc < 128; kc += 4) {
                    #pragma unroll
                    for (int u = 0; u < 4; u++) {
                        float wv = pf[u];
                        pf[u] = __ldg(wp + (size_t)((kc + 4 + u) & 127) * NM);
                        fma16(acc, saw + (kc + u) * 32, wv);
                    }
                }
            }

            // ---- cross-kq reduction (8 sets, rotated banks) ----
            __syncthreads();
            u64* Rsm = (u64*)sA;
            {
                int base = kq * 1024 + nloc * 16;
                #pragma unroll
                for (int a = 0; a < 16; a++)
                    Rsm[base + ((a + nloc) & 15)] = acc[a];
            }
            __syncthreads();
            {
                u64* pout = (u64*)(g_partial[par][mm]) + (size_t)blk * 1024;
                #pragma unroll
                for (int r = 0; r < 2; r++) {
                    int o = tid + r * NTHR;
                    int idx = (o & ~15) | (((o & 15) + (o >> 4)) & 15);
                    u64 v0 = Rsm[0 * 1024 + idx], v1 = Rsm[1 * 1024 + idx];
                    u64 v2 = Rsm[2 * 1024 + idx], v3 = Rsm[3 * 1024 + idx];
                    u64 v4 = Rsm[4 * 1024 + idx], v5 = Rsm[5 * 1024 + idx];
                    u64 v6 = Rsm[6 * 1024 + idx], v7 = Rsm[7 * 1024 + idx];
                    ADD2(v0, v4); ADD2(v1, v5); ADD2(v2, v6); ADD2(v3, v7);
                    ADD2(v0, v2); ADD2(v1, v3); ADD2(v0, v1);
                    pout[o] = v0;
                }
            }
            __syncthreads();
        }

        // ---- arrive barrier 1 ----
        if (tid == 0) { __threadfence(); red_add(&g_bar1[blockIdx.x & 7]); }

        if (finalIter) {
            if (isH2C) {   // final combine writes out[:, T-1, :]
                wait1_block(144u * (unsigned)(t + 1));
                const float* p6 = g_partial[par][6];
                const float* p7 = g_partial[par][7];
                const float* p8 = g_partial[par][8];
                #pragma unroll
                for (int i = 0; i < 2; i++) {
                    int nn = n0c + cw * 2 + i;
                    int off = nn * NB + lane;
                    float v = tanhf(p6[off] + p7[off] + p8[off] + b2[nn]);
                    float h2v = 0.5f * g_h2T[par][off] + 0.5f * v;
                    tile[(nn - n0c) * 33 + lane] = h2v;
                }
                __syncthreads();
                #pragma unroll
                for (int i = 0; i < 2; i++) {
                    int b = cw * 2 + i;
                    out[(size_t)b * T_STEPS * NM + (size_t)(t - 1) * NM + n0c + lane] =
                        tile[lane * 33 + b];
                }
            }
            return;
        }

        // ---- tail: one wait per block + hidden work ----
        const int nxt = (t + 1) & 1;
        if (isH1C) {
            wait1_block(144u * (unsigned)(t + 1));
            const float* p3 = g_partial[par][3];
            const float* p4 = g_partial[par][4];
            const float* p5 = g_partial[par][5];
            #pragma unroll
            for (int i = 0; i < 2; i++) {
                int nn = n0c + cw * 2 + i;
                int off = nn * NB + lane;
                float v = tanhf(p3[off] + p4[off] + p5[off] + b1[nn]);
                g_h1T[nxt][off] = 0.5f * g_h1T[par][off] + 0.5f * v;
            }
            __syncthreads();
            if (tid == 0) { __threadfence(); red_add(&g_bar2[blockIdx.x & 3]); }
            #pragma unroll
            for (int i = 0; i < 16; i++) acc[i] = 0ull;
        } else if (isH2C) {
            wait1_block(144u * (unsigned)(t + 1));
            const float* p6 = g_partial[par][6];
            const float* p7 = g_partial[par][7];
            const float* p8 = g_partial[par][8];
            #pragma unroll
            for (int i = 0; i < 2; i++) {
                int nn = n0c + cw * 2 + i;
                int off = nn * NB + lane;
                float v = tanhf(p6[off] + p7[off] + p8[off] + b2[nn]);
                if (t >= 1) {
                    float h2v = 0.5f * g_h2T[par][off] + 0.5f * v;
                    g_h2T[nxt][off] = h2v;
                    tile[(nn - n0c) * 33 + lane] = h2v;
                }
            }
            __syncthreads();
            if (tid == 0) { __threadfence(); red_add(&g_bar2[blockIdx.x & 3]); }
            if (t >= 1) {
                #pragma unroll
                for (int i = 0; i < 2; i++) {
                    int b = cw * 2 + i;
                    out[(size_t)b * T_STEPS * NM + (size_t)(t - 1) * NM + n0c + lane] =
                        tile[lane * 33 + b];
                }
            }
            #pragma unroll
            for (int i = 0; i < 16; i++) acc[i] = 0ull;
        } else if (!isHblk) {
            // mm 0,1: wait1, then x-phase for t+1 hidden after the wait
            wait1_block(144u * (unsigned)(t + 1));
            #pragma unroll
            for (int i = 0; i < 16; i++) acc[i] = 0ull;
            if (t + 1 < T_STEPS) {
                const float4* xs = (const float4*)(g_xT + (size_t)(t + 1) * (NI * NB));
                ((float4*)sX)[tid] = xs[tid];
                __syncthreads();
                const float* wx = Wx + (size_t)(kq * 8) * NM + n;
                #pragma unroll
                for (int u = 0; u < 8; u++)
                    fma16(acc, sX + (kq * 8 + u) * 32, __ldg(wx + (size_t)u * NM));
            }
        } else {
            // h-blocks (mm 3,6,7): x-phase (mm3) inside the barrier-2 wait window
            #pragma unroll
            for (int i = 0; i < 16; i++) acc[i] = 0ull;
            if (mm == 3 && t + 1 < T_STEPS) {
                const float4* xs = (const float4*)(g_xT + (size_t)(t + 1) * (NI * NB));
                ((float4*)sX)[tid] = xs[tid];
                __syncthreads();
                const float* wx = Wx + (size_t)(kq * 8) * NM + n;
                #pragma unroll
                for (int u = 0; u < 8; u++)
                    fma16(acc, sX + (kq * 8 + u) * 32, __ldg(wx + (size_t)u * NM));
            }
            wait2_block(64u * (unsigned)(t + 1));
        }
    }
}

// ---------------- launch ----------------
extern "C" void kernel_launch(void* const* d_in, const int* in_sizes, int n_in,
                              void* d_out, int out_size) {
    const float* x    = (const float*)d_in[0];
    const float* Wm1  = (const float*)d_in[1];
    const float* Vm1  = (const float*)d_in[2];
    const float* Wm2  = (const float*)d_in[3];
    const float* Vm2  = (const float*)d_in[4];
    const float* Win1 = (const float*)d_in[5];
    const float* Wh1  = (const float*)d_in[6];
    const float* Wmh1 = (const float*)d_in[7];
    const float* b1   = (const float*)d_in[8];
    const float* Win2 = (const float*)d_in[9];
    const float* Wh2  = (const float*)d_in[10];
    const float* Wmh2 = (const float*)d_in[11];
    const float* b2   = (const float*)d_in[12];
    float* out = (float*)d_out;

    transp_all_kernel<<<dim3(4096, 7), 256>>>(Vm1, Vm2, Wh1, Win2, Wh2, Wmh2, Wm1);
    pre_wave1_kernel<<<dim3(16, 16, 3), dim3(16, 16)>>>(Wm2, Vm1, Wmh1, Vm2, Wm1);
    pre_wave2_kernel<<<dim3(16, 16, 2), dim3(16, 16)>>>(Wmh1, Win1);
    xtrans_kernel<<<(NB * T_STEPS * NI + 255) / 256, 256>>>(x);
    zero_states_kernel<<<256, 256>>>();

    const int SMEM = (NM * NB + NI * NB) * 4;   // 136 KB
    cudaFuncSetAttribute(persist_kernel,
                         cudaFuncAttributeMaxDynamicSharedMemorySize, SMEM);
    persist_kernel<<<NBLK, NTHR, SMEM>>>(b1, b2, out);
}